// round 3
// baseline (speedup 1.0000x reference)
#include <cuda_runtime.h>
#include <cuda_bf16.h>

// Problem dims
#define BB    8
#define TOUT  256
#define TIN   512
#define LL    128
#define DIN   128
#define DATT  128
#define GG    512   // 4*L

// Scratch (device globals: no allocation allowed)
__device__ float g_keys[BB * TIN * LL];    // 2 MB
__device__ float g_xz[BB * TOUT * GG];     // 4 MB

__device__ __forceinline__ float fast_tanh(float x) {
    float y;
    asm("tanh.approx.f32 %0, %1;" : "=f"(y) : "f"(x));
    return y;
}
__device__ __forceinline__ float sigm_acc(float x) {
    return 1.0f / (1.0f + __expf(-x));
}
__device__ __forceinline__ float tanh_acc(float x) {
    return 2.0f / (1.0f + __expf(-2.0f * x)) - 1.0f;
}

// ---------------------------------------------------------------------------
// Kernel 1: xz = inputs @ Wk + bias   (2048 rows x 512 cols, K=128)
// grid 128, block 512, 16 rows per CTA
// ---------------------------------------------------------------------------
__global__ void xz_kernel(const float* __restrict__ inp,
                          const float* __restrict__ Wk,
                          const float* __restrict__ bias) {
    __shared__ float a_s[16][128];
    const int tid = threadIdx.x;
    const int row0 = blockIdx.x * 16;

    // cooperative load: 2048 floats = 512 float4, one per thread
    const float4* src = (const float4*)(inp + row0 * DIN);
    ((float4*)&a_s[0][0])[tid] = src[tid];
    __syncthreads();

    float acc[16];
    float bj = bias[tid];
#pragma unroll
    for (int r = 0; r < 16; r++) acc[r] = bj;

    for (int d = 0; d < 128; d += 4) {
        float w0 = Wk[(d + 0) * GG + tid];
        float w1 = Wk[(d + 1) * GG + tid];
        float w2 = Wk[(d + 2) * GG + tid];
        float w3 = Wk[(d + 3) * GG + tid];
#pragma unroll
        for (int r = 0; r < 16; r++) {
            float4 a = *(const float4*)&a_s[r][d];
            acc[r] += a.x * w0 + a.y * w1 + a.z * w2 + a.w * w3;
        }
    }
#pragma unroll
    for (int r = 0; r < 16; r++)
        g_xz[(row0 + r) * GG + tid] = acc[r];
}

// ---------------------------------------------------------------------------
// Kernel 2: keys = attended @ W1 + b1  (4096 rows x 128 cols, K=128)
// grid 256, block 128, 16 rows per CTA
// ---------------------------------------------------------------------------
__global__ void keys_kernel(const float* __restrict__ att,
                            const float* __restrict__ W1,
                            const float* __restrict__ b1) {
    __shared__ float a_s[16][128];
    const int tid = threadIdx.x;
    const int row0 = blockIdx.x * 16;

    const float4* src = (const float4*)(att + row0 * DATT);
    float4* dst = (float4*)&a_s[0][0];
    for (int i = tid; i < 512; i += 128) dst[i] = src[i];
    __syncthreads();

    float acc[16];
    float bj = b1[tid];
#pragma unroll
    for (int r = 0; r < 16; r++) acc[r] = bj;

    for (int d = 0; d < 128; d += 4) {
        float w0 = W1[(d + 0) * LL + tid];
        float w1 = W1[(d + 1) * LL + tid];
        float w2 = W1[(d + 2) * LL + tid];
        float w3 = W1[(d + 3) * LL + tid];
#pragma unroll
        for (int r = 0; r < 16; r++) {
            float4 a = *(const float4*)&a_s[r][d];
            acc[r] += a.x * w0 + a.y * w1 + a.z * w2 + a.w * w3;
        }
    }
#pragma unroll
    for (int r = 0; r < 16; r++)
        g_keys[(row0 + r) * LL + tid] = acc[r];
}

// ---------------------------------------------------------------------------
// Kernel 3: LSTM scan. grid 8 (one CTA per batch), block 512.
// Wr rows 0..63 in registers (64 regs/thread), rows 64..127 in smem
// (column-major, pad 68 floats/col -> conflict-free float4 reads).
// Writes x into out[b,t,0:128]; h,c tails at the end.
// Smem: 512*68 + 128 + 512 floats = 141,824 B (dynamic).
// ---------------------------------------------------------------------------
#define LSTM_SMEM ((512 * 68 + 128 + 512) * 4)

__global__ void lstm_kernel(const float* __restrict__ Wr,
                            float* __restrict__ out) {
    extern __shared__ float sm[];
    float* whi = sm;                   // [512][68]
    float* h_s = sm + 512 * 68;        // [128]
    float* z_s = h_s + 128;            // [512]

    const int tid = threadIdx.x;
    const int b = blockIdx.x;

    // low 64 rows of this thread's column into registers
    float w[64];
#pragma unroll
    for (int j = 0; j < 64; j++) w[j] = Wr[j * GG + tid];

    // high 64 rows into smem (column-major padded)
    for (int i = tid; i < 64 * 512; i += 512) {
        int j = i >> 9;          // row - 64
        int col = i & 511;
        whi[col * 68 + j] = Wr[(64 + j) * GG + col];
    }
    if (tid < 128) h_s[tid] = 0.0f;
    float c = 0.0f;
    __syncthreads();

    const float* xzb = g_xz + b * TOUT * GG;
    float* outx = out + b * TOUT * 256;
    float xz_next = xzb[tid];

    for (int t = 0; t < TOUT; t++) {
        float acc0 = xz_next;
        float acc1 = 0.0f;
        int tn = (t < TOUT - 1) ? (t + 1) : t;
        xz_next = xzb[tn * GG + tid];

        const float4* h4 = (const float4*)h_s;
        const float4* w4 = (const float4*)(whi + tid * 68);
#pragma unroll
        for (int j = 0; j < 16; j++) {
            float4 hv = h4[j];
            acc0 += w[4 * j + 0] * hv.x + w[4 * j + 1] * hv.y;
            acc1 += w[4 * j + 2] * hv.z + w[4 * j + 3] * hv.w;
        }
#pragma unroll
        for (int j = 0; j < 16; j++) {
            float4 hv = h4[16 + j];
            float4 wv = w4[j];
            acc0 += wv.x * hv.x + wv.y * hv.y;
            acc1 += wv.z * hv.z + wv.w * hv.w;
        }
        z_s[tid] = acc0 + acc1;
        __syncthreads();

        if (tid < 128) {
            float zi = z_s[tid];
            float zf = z_s[tid + 128];
            float zg = z_s[tid + 256];
            float zo = z_s[tid + 384];
            c = sigm_acc(zf) * c + sigm_acc(zi) * tanh_acc(zg);
            float h = sigm_acc(zo) * tanh_acc(c);
            h_s[tid] = h;
            outx[t * 256 + tid] = h;   // x part of out
        }
        __syncthreads();
    }

    if (tid < 128) {
        out[BB * TOUT * 256 + b * LL + tid] = h_s[tid];            // h_T
        out[BB * TOUT * 256 + BB * LL + b * LL + tid] = c;         // c_T
    }
}

// ---------------------------------------------------------------------------
// Kernel 4: fused q = x@W2+b2, Bahdanau scores, online softmax, weighted sum.
// grid (32, 8): blockIdx.y = batch, blockIdx.x = tile of 8 q-rows.
// block 256: warp w handles q-row (tile*8 + w); lanes parallel over k.
// Smem: keys chunk [128][132], att chunk [128][132], q[8][128], w3[128]
//      = 139,776 B (dynamic).
// ---------------------------------------------------------------------------
#define ATTN_SMEM ((128 * 132 * 2 + 8 * 128 + 128) * 4)

__global__ void attn_kernel(const float* __restrict__ attg,
                            const float* __restrict__ W2,
                            const float* __restrict__ b2,
                            const float* __restrict__ W3,
                            float* __restrict__ out) {
    extern __shared__ float sm[];
    float* keys_s = sm;                 // 128*132
    float* att_s  = sm + 128 * 132;     // 128*132
    float* q_s    = sm + 2 * 128 * 132; // 8*128
    float* w3_s   = q_s + 8 * 128;      // 128

    const int tid = threadIdx.x;
    const int lane = tid & 31;
    const int wid = tid >> 5;
    const int b = blockIdx.y;
    const int t0 = blockIdx.x * 8;

    // ---- prologue: stage W2 into keys_s (pad 132), x rows into att_s ----
    if (tid < 128) w3_s[tid] = W3[tid];
    for (int i = tid; i < 128 * 128; i += 256) {
        int d = i >> 7, cc = i & 127;
        keys_s[d * 132 + cc] = W2[i];
    }
    for (int i = tid; i < 8 * 128; i += 256) {
        int tl = i >> 7, dd = i & 127;
        att_s[i] = out[b * (TOUT * 256) + (t0 + tl) * 256 + dd];  // x
    }
    __syncthreads();

    // q = x @ W2 + b2 (4 outputs per thread)
#pragma unroll
    for (int r = 0; r < 4; r++) {
        int i = r * 256 + tid;
        int tq = i >> 7, cc = i & 127;
        float acc = b2[cc];
        const float* xr = att_s + tq * 128;
        for (int d = 0; d < 128; d += 2) {
            acc += xr[d] * keys_s[d * 132 + cc];
            acc += xr[d + 1] * keys_s[(d + 1) * 132 + cc];
        }
        q_s[tq * 128 + cc] = acc;
    }

    // per-warp online softmax state
    float m = -1e30f;
    float denom = 0.0f;
    float a0 = 0.f, a1 = 0.f, a2 = 0.f, a3 = 0.f;
    const float4* qrow4 = (const float4*)(q_s + wid * 128);
    const float4* w34 = (const float4*)w3_s;

    for (int kc = 0; kc < 4; kc++) {
        __syncthreads();  // previous chunk consumers done / q ready
        // load keys & attended chunk (128 rows x 128 cols each)
        const float4* ksrc = (const float4*)(g_keys + b * TIN * LL + kc * 128 * LL);
        const float4* asrc = (const float4*)(attg + b * TIN * DATT + kc * 128 * DATT);
        for (int i = tid; i < 4096; i += 256) {
            int r = i >> 5, c4 = i & 31;
            *(float4*)&keys_s[r * 132 + c4 * 4] = ksrc[i];
            *(float4*)&att_s[r * 132 + c4 * 4] = asrc[i];
        }
        __syncthreads();

        // scores: lane handles k = ks*32 + lane
        float p[4];
        float smax = -1e30f;
#pragma unroll
        for (int ks = 0; ks < 4; ks++) {
            int k = ks * 32 + lane;
            const float4* krow = (const float4*)(keys_s + k * 132);
            float d0 = 0.f, d1 = 0.f;
#pragma unroll
            for (int l4 = 0; l4 < 32; l4 += 2) {
                float4 kv = krow[l4];
                float4 qv = qrow4[l4];
                float4 wv = w34[l4];
                d0 += fast_tanh(kv.x + qv.x) * wv.x + fast_tanh(kv.y + qv.y) * wv.y
                    + fast_tanh(kv.z + qv.z) * wv.z + fast_tanh(kv.w + qv.w) * wv.w;
                kv = krow[l4 + 1]; qv = qrow4[l4 + 1]; wv = w34[l4 + 1];
                d1 += fast_tanh(kv.x + qv.x) * wv.x + fast_tanh(kv.y + qv.y) * wv.y
                    + fast_tanh(kv.z + qv.z) * wv.z + fast_tanh(kv.w + qv.w) * wv.w;
            }
            p[ks] = d0 + d1;
            smax = fmaxf(smax, p[ks]);
        }
#pragma unroll
        for (int off = 16; off > 0; off >>= 1)
            smax = fmaxf(smax, __shfl_xor_sync(0xffffffffu, smax, off));

        float mnew = fmaxf(m, smax);
        float scale = __expf(m - mnew);
        denom *= scale; a0 *= scale; a1 *= scale; a2 *= scale; a3 *= scale;
#pragma unroll
        for (int ks = 0; ks < 4; ks++) {
            p[ks] = __expf(p[ks] - mnew);
            denom += p[ks];
        }
        m = mnew;

        // weighted accumulate: acc[d] += p_k * att[k][d]
#pragma unroll
        for (int ks = 0; ks < 4; ks++) {
            for (int sl = 0; sl < 32; sl++) {
                float pv = __shfl_sync(0xffffffffu, p[ks], sl);
                const float* ar = att_s + (ks * 32 + sl) * 132;
                a0 += pv * ar[lane];
                a1 += pv * ar[lane + 32];
                a2 += pv * ar[lane + 64];
                a3 += pv * ar[lane + 96];
            }
        }
    }

    // reduce denom across lanes, normalize, write weighted part
#pragma unroll
    for (int off = 16; off > 0; off >>= 1)
        denom += __shfl_xor_sync(0xffffffffu, denom, off);
    float inv = 1.0f / denom;

    float* od = out + b * (TOUT * 256) + (t0 + wid) * 256 + 128;
    od[lane] = a0 * inv;
    od[lane + 32] = a1 * inv;
    od[lane + 64] = a2 * inv;
    od[lane + 96] = a3 * inv;
}

// ---------------------------------------------------------------------------
extern "C" void kernel_launch(void* const* d_in, const int* in_sizes, int n_in,
                              void* d_out, int out_size) {
    const float* inputs   = (const float*)d_in[0];
    const float* attended = (const float*)d_in[1];
    const float* Wk       = (const float*)d_in[2];
    const float* Wr       = (const float*)d_in[3];
    const float* bias     = (const float*)d_in[4];
    const float* W1       = (const float*)d_in[5];
    const float* b1       = (const float*)d_in[6];
    const float* W2       = (const float*)d_in[7];
    const float* b2       = (const float*)d_in[8];
    const float* W3       = (const float*)d_in[9];
    // d_in[10] = b3: constant shift of scores -> softmax-invariant, unused.
    float* out = (float*)d_out;

    cudaFuncSetAttribute(lstm_kernel, cudaFuncAttributeMaxDynamicSharedMemorySize, LSTM_SMEM);
    cudaFuncSetAttribute(attn_kernel, cudaFuncAttributeMaxDynamicSharedMemorySize, ATTN_SMEM);

    xz_kernel<<<128, 512>>>(inputs, Wk, bias);
    keys_kernel<<<256, 128>>>(attended, W1, b1);
    lstm_kernel<<<8, 512, LSTM_SMEM>>>(Wr, out);
    attn_kernel<<<dim3(32, 8), 256, ATTN_SMEM>>>(attended, W2, b2, W3, out);
}

// round 6
// speedup vs baseline: 1.3760x; 1.3760x over previous
#include <cuda_runtime.h>
#include <cuda_bf16.h>

// Problem dims
#define BB    8
#define TOUT  256
#define TIN   512
#define LL    128
#define DIN   128
#define DATT  128
#define GG    512   // 4*L

// Scratch (device globals: no allocation allowed)
__device__ float g_keys[BB * TIN * LL];    // 2 MB
__device__ float g_xz[BB * TOUT * GG];     // 4 MB

__device__ __forceinline__ float fast_tanh(float x) {
    float y;
    asm("tanh.approx.f32 %0, %1;" : "=f"(y) : "f"(x));
    return y;
}
__device__ __forceinline__ float sigm_acc(float x) {
    return 1.0f / (1.0f + __expf(-x));
}
__device__ __forceinline__ float tanh_acc(float x) {
    return 2.0f / (1.0f + __expf(-2.0f * x)) - 1.0f;
}
// packed f32x2 fma (sm_103a): d = a*b + c lanewise on 2 floats in a u64
__device__ __forceinline__ unsigned long long ffma2(unsigned long long a,
                                                    unsigned long long b,
                                                    unsigned long long c) {
    unsigned long long d;
    asm("fma.rn.f32x2 %0, %1, %2, %3;" : "=l"(d) : "l"(a), "l"(b), "l"(c));
    return d;
}
__device__ __forceinline__ unsigned long long pack2(float lo, float hi) {
    unsigned long long p;
    asm("mov.b64 %0, {%1, %2};" : "=l"(p) : "f"(lo), "f"(hi));
    return p;
}
__device__ __forceinline__ float2 unpack2(unsigned long long p) {
    float lo, hi;
    asm("mov.b64 {%0, %1}, %2;" : "=f"(lo), "=f"(hi) : "l"(p));
    return make_float2(lo, hi);
}

// ---------------------------------------------------------------------------
// Kernel 1: xz = inputs @ Wk + bias   (2048 rows x 512 cols, K=128)
// ---------------------------------------------------------------------------
__global__ void xz_kernel(const float* __restrict__ inp,
                          const float* __restrict__ Wk,
                          const float* __restrict__ bias) {
    __shared__ float a_s[16][128];
    const int tid = threadIdx.x;
    const int row0 = blockIdx.x * 16;

    const float4* src = (const float4*)(inp + row0 * DIN);
    ((float4*)&a_s[0][0])[tid] = src[tid];
    __syncthreads();

    float acc[16];
    float bj = bias[tid];
#pragma unroll
    for (int r = 0; r < 16; r++) acc[r] = bj;

    for (int d = 0; d < 128; d += 4) {
        float w0 = Wk[(d + 0) * GG + tid];
        float w1 = Wk[(d + 1) * GG + tid];
        float w2 = Wk[(d + 2) * GG + tid];
        float w3 = Wk[(d + 3) * GG + tid];
#pragma unroll
        for (int r = 0; r < 16; r++) {
            float4 a = *(const float4*)&a_s[r][d];
            acc[r] += a.x * w0 + a.y * w1 + a.z * w2 + a.w * w3;
        }
    }
#pragma unroll
    for (int r = 0; r < 16; r++)
        g_xz[(row0 + r) * GG + tid] = acc[r];
}

// ---------------------------------------------------------------------------
// Kernel 2: keys = attended @ W1 + b1  (4096 rows x 128 cols, K=128)
// ---------------------------------------------------------------------------
__global__ void keys_kernel(const float* __restrict__ att,
                            const float* __restrict__ W1,
                            const float* __restrict__ b1) {
    __shared__ float a_s[16][128];
    const int tid = threadIdx.x;
    const int row0 = blockIdx.x * 16;

    const float4* src = (const float4*)(att + row0 * DATT);
    float4* dst = (float4*)&a_s[0][0];
    for (int i = tid; i < 512; i += 128) dst[i] = src[i];
    __syncthreads();

    float acc[16];
    float bj = b1[tid];
#pragma unroll
    for (int r = 0; r < 16; r++) acc[r] = bj;

    for (int d = 0; d < 128; d += 4) {
        float w0 = W1[(d + 0) * LL + tid];
        float w1 = W1[(d + 1) * LL + tid];
        float w2 = W1[(d + 2) * LL + tid];
        float w3 = W1[(d + 3) * LL + tid];
#pragma unroll
        for (int r = 0; r < 16; r++) {
            float4 a = *(const float4*)&a_s[r][d];
            acc[r] += a.x * w0 + a.y * w1 + a.z * w2 + a.w * w3;
        }
    }
#pragma unroll
    for (int r = 0; r < 16; r++)
        g_keys[(row0 + r) * LL + tid] = acc[r];
}

// ---------------------------------------------------------------------------
// Kernel 3: LSTM scan v2. grid 8 (one CTA per batch), block 512.
// Wr rows 0..91 in registers as 46 packed f32x2 pairs per thread,
// rows 92..127 in smem (per-column packed pairs, stride 44 floats =
// 11x16B granules, odd -> conflict-free LDS.128).
// fma.rn.f32x2 halves the FMA issue count.
// Gate nonlinearities distributed across all 512 threads.
// ---------------------------------------------------------------------------
#define WSM_STRIDE 44
#define LSTM_SMEM ((512 * WSM_STRIDE + 128 + 512) * 4)   // 92,672 B

__global__ void __launch_bounds__(512, 1)
lstm_kernel(const float* __restrict__ Wr, float* __restrict__ out) {
    extern __shared__ float sm[];
    float* wsm = sm;                        // [512][44] packed pairs, rows 92..127
    float* h_s = sm + 512 * WSM_STRIDE;     // [128]
    float* a_s = h_s + 128;                 // [512] activated gates

    const int tid = threadIdx.x;
    const int b = blockIdx.x;

    // rows 0..91 of this thread's column -> 46 packed register pairs
    unsigned long long w[46];
#pragma unroll
    for (int j = 0; j < 46; j++) {
        float lo = Wr[(2 * j) * GG + tid];
        float hi = Wr[(2 * j + 1) * GG + tid];
        w[j] = pack2(lo, hi);
    }
    // rows 92..127 -> smem packed pairs (18 pairs per column)
#pragma unroll
    for (int p = 0; p < 18; p++) {
        wsm[tid * WSM_STRIDE + 2 * p]     = Wr[(92 + 2 * p) * GG + tid];
        wsm[tid * WSM_STRIDE + 2 * p + 1] = Wr[(93 + 2 * p) * GG + tid];
    }
    if (tid < 128) h_s[tid] = 0.0f;
    float c = 0.0f;
    __syncthreads();

    const float* xzb = g_xz + b * TOUT * GG;
    float* outx = out + b * TOUT * 256;
    float xz_cur = xzb[tid];

    const bool is_g = (tid >= 256) && (tid < 384);

    for (int t = 0; t < TOUT; t++) {
        unsigned long long a0 = pack2(xz_cur, 0.0f);
        unsigned long long a1 = 0ULL, a2 = 0ULL, a3 = 0ULL;

        const ulonglong2* h2 = (const ulonglong2*)h_s;
        // register-weight part: h[0..91]
#pragma unroll
        for (int j = 0; j < 23; j++) {
            ulonglong2 hv = h2[j];
            a0 = ffma2(w[2 * j],     hv.x, a0);
            a1 = ffma2(w[2 * j + 1], hv.y, a1);
        }
        // smem-weight part: h[92..127]
        const ulonglong2* wp = (const ulonglong2*)(wsm + tid * WSM_STRIDE);
#pragma unroll
        for (int r = 0; r < 9; r++) {
            ulonglong2 hv = h2[23 + r];
            ulonglong2 wv = wp[r];
            a2 = ffma2(wv.x, hv.x, a2);
            a3 = ffma2(wv.y, hv.y, a3);
        }

        float2 f0 = unpack2(a0), f1 = unpack2(a1), f2 = unpack2(a2), f3 = unpack2(a3);
        float z = ((f0.x + f0.y) + (f1.x + f1.y)) + ((f2.x + f2.y) + (f3.x + f3.y));

        // prefetch next step's xz while z settles
        if (t + 1 < TOUT) xz_cur = xzb[(t + 1) * GG + tid];

        // distributed gate nonlinearity: own z only
        a_s[tid] = is_g ? tanh_acc(z) : sigm_acc(z);
        __syncthreads();

        if (tid < 128) {
            float ai = a_s[tid];
            float af = a_s[tid + 128];
            float ag = a_s[tid + 256];
            float ao = a_s[tid + 384];
            c = af * c + ai * ag;
            float h = ao * tanh_acc(c);
            h_s[tid] = h;
            outx[t * 256 + tid] = h;
        }
        __syncthreads();
    }

    if (tid < 128) {
        out[BB * TOUT * 256 + b * LL + tid] = h_s[tid];            // h_T
        out[BB * TOUT * 256 + BB * LL + b * LL + tid] = c;         // c_T
    }
}

// ---------------------------------------------------------------------------
// Kernel 4 v2: fused q = x@W2+b2, Bahdanau scores, online softmax, weighted sum.
// grid (16, 8) = 128 CTAs (single wave); block 256 = 8 warps.
// Each CTA: 16 q-rows; each warp: 2 q-rows (keys smem reads amortized 2x).
// p held in smem (broadcast reads), weighted sum via float4 att reads.
// Smem: keys[128][132] + att[128][132] + q[16][128] + p[16][128] + w3[128]
//       = 152,064 B -> 1 CTA/SM, registers unconstrained.
// ---------------------------------------------------------------------------
#define ATTN_SMEM ((128 * 132 * 2 + 16 * 128 + 16 * 128 + 128) * 4)

__global__ void __launch_bounds__(256, 1)
attn_kernel(const float* __restrict__ attg,
            const float* __restrict__ W2,
            const float* __restrict__ b2,
            const float* __restrict__ W3,
            float* __restrict__ out) {
    extern __shared__ float sm[];
    float* keys_s = sm;                     // 128*132
    float* att_s  = sm + 128 * 132;         // 128*132
    float* q_s    = sm + 2 * 128 * 132;     // 16*128
    float* p_s    = q_s + 16 * 128;         // 16*128
    float* w3_s   = p_s + 16 * 128;         // 128

    const int tid = threadIdx.x;
    const int lane = tid & 31;
    const int wid = tid >> 5;
    const int b = blockIdx.y;
    const int t0 = blockIdx.x * 16;

    // ---- prologue: stage W2 into keys_s (pad 132), x rows into att_s ----
    if (tid < 128) w3_s[tid] = W3[tid];
    for (int i = tid; i < 128 * 128; i += 256) {
        int d = i >> 7, cc = i & 127;
        keys_s[d * 132 + cc] = W2[i];
    }
    for (int i = tid; i < 16 * 128; i += 256) {
        int tq = i >> 7, dd = i & 127;
        att_s[tq * 132 + dd] = out[b * (TOUT * 256) + (t0 + tq) * 256 + dd];  // x
    }
    __syncthreads();

    // q = x @ W2 + b2 : 16 rows, 8 outputs per thread
#pragma unroll
    for (int r = 0; r < 8; r++) {
        int i = r * 256 + tid;
        int tq = i >> 7, cc = i & 127;
        float acc = b2[cc];
        const float* xr = att_s + tq * 132;
#pragma unroll 8
        for (int d = 0; d < 128; d++)
            acc += xr[d] * keys_s[d * 132 + cc];
        q_s[tq * 128 + cc] = acc;
    }

    // per-warp state for 2 q-rows
    const int r0 = 2 * wid, r1 = 2 * wid + 1;
    float m0 = -1e30f, m1 = -1e30f;
    float den0 = 0.0f, den1 = 0.0f;
    float4 acc0 = make_float4(0.f, 0.f, 0.f, 0.f);
    float4 acc1 = make_float4(0.f, 0.f, 0.f, 0.f);

    const float4* q0 = (const float4*)(q_s + r0 * 128);
    const float4* q1 = (const float4*)(q_s + r1 * 128);
    const float4* w34 = (const float4*)w3_s;

    for (int kc = 0; kc < 4; kc++) {
        __syncthreads();  // previous chunk fully consumed (and q ready)
        const float4* ksrc = (const float4*)(g_keys + b * TIN * LL + kc * 128 * LL);
        const float4* asrc = (const float4*)(attg + b * TIN * DATT + kc * 128 * DATT);
        for (int i = tid; i < 4096; i += 256) {
            int r = i >> 5, c4 = i & 31;
            *(float4*)&keys_s[r * 132 + c4 * 4] = ksrc[i];
            *(float4*)&att_s[r * 132 + c4 * 4] = asrc[i];
        }
        __syncthreads();

        // scores for 2 q-rows; lane covers k = ks*32+lane
        float p0[4] = {0.f, 0.f, 0.f, 0.f};
        float p1[4] = {0.f, 0.f, 0.f, 0.f};
#pragma unroll 4
        for (int l4 = 0; l4 < 32; l4++) {
            float4 wv  = w34[l4];
            float4 qv0 = q0[l4];
            float4 qv1 = q1[l4];
#pragma unroll
            for (int ks = 0; ks < 4; ks++) {
                float4 kv = *(const float4*)(keys_s + (ks * 32 + lane) * 132 + l4 * 4);
                p0[ks] += fast_tanh(kv.x + qv0.x) * wv.x + fast_tanh(kv.y + qv0.y) * wv.y
                        + fast_tanh(kv.z + qv0.z) * wv.z + fast_tanh(kv.w + qv0.w) * wv.w;
                p1[ks] += fast_tanh(kv.x + qv1.x) * wv.x + fast_tanh(kv.y + qv1.y) * wv.y
                        + fast_tanh(kv.z + qv1.z) * wv.z + fast_tanh(kv.w + qv1.w) * wv.w;
            }
        }

        // warp max
        float s0 = fmaxf(fmaxf(p0[0], p0[1]), fmaxf(p0[2], p0[3]));
        float s1 = fmaxf(fmaxf(p1[0], p1[1]), fmaxf(p1[2], p1[3]));
#pragma unroll
        for (int off = 16; off > 0; off >>= 1) {
            s0 = fmaxf(s0, __shfl_xor_sync(0xffffffffu, s0, off));
            s1 = fmaxf(s1, __shfl_xor_sync(0xffffffffu, s1, off));
        }
        float mn0 = fmaxf(m0, s0), mn1 = fmaxf(m1, s1);
        float sc0 = __expf(m0 - mn0), sc1 = __expf(m1 - mn1);
        den0 *= sc0; den1 *= sc1;
        acc0.x *= sc0; acc0.y *= sc0; acc0.z *= sc0; acc0.w *= sc0;
        acc1.x *= sc1; acc1.y *= sc1; acc1.z *= sc1; acc1.w *= sc1;
        m0 = mn0; m1 = mn1;

#pragma unroll
        for (int ks = 0; ks < 4; ks++) {
            float e0 = __expf(p0[ks] - mn0);
            float e1 = __expf(p1[ks] - mn1);
            den0 += e0; den1 += e1;
            p_s[r0 * 128 + ks * 32 + lane] = e0;
            p_s[r1 * 128 + ks * 32 + lane] = e1;
        }
        __syncwarp();   // cross-lane p_s visibility within the warp

        // weighted accumulate: acc[d] += p[k] * att[k][d], lane owns d=lane*4..+3
        const float* pr0 = p_s + r0 * 128;
        const float* pr1 = p_s + r1 * 128;
#pragma unroll 2
        for (int k = 0; k < 128; k++) {
            float pv0 = pr0[k];
            float pv1 = pr1[k];
            float4 av = *(const float4*)(att_s + k * 132 + lane * 4);
            acc0.x += pv0 * av.x; acc0.y += pv0 * av.y;
            acc0.z += pv0 * av.z; acc0.w += pv0 * av.w;
            acc1.x += pv1 * av.x; acc1.y += pv1 * av.y;
            acc1.z += pv1 * av.z; acc1.w += pv1 * av.w;
        }
    }

    // reduce denominators across lanes, normalize, write weighted part
#pragma unroll
    for (int off = 16; off > 0; off >>= 1) {
        den0 += __shfl_xor_sync(0xffffffffu, den0, off);
        den1 += __shfl_xor_sync(0xffffffffu, den1, off);
    }
    float inv0 = 1.0f / den0, inv1 = 1.0f / den1;

    float* od0 = out + b * (TOUT * 256) + (t0 + r0) * 256 + 128;
    float* od1 = out + b * (TOUT * 256) + (t0 + r1) * 256 + 128;
    *(float4*)(od0 + lane * 4) = make_float4(acc0.x * inv0, acc0.y * inv0,
                                             acc0.z * inv0, acc0.w * inv0);
    *(float4*)(od1 + lane * 4) = make_float4(acc1.x * inv1, acc1.y * inv1,
                                             acc1.z * inv1, acc1.w * inv1);
}

// ---------------------------------------------------------------------------
extern "C" void kernel_launch(void* const* d_in, const int* in_sizes, int n_in,
                              void* d_out, int out_size) {
    const float* inputs   = (const float*)d_in[0];
    const float* attended = (const float*)d_in[1];
    const float* Wk       = (const float*)d_in[2];
    const float* Wr       = (const float*)d_in[3];
    const float* bias     = (const float*)d_in[4];
    const float* W1       = (const float*)d_in[5];
    const float* b1       = (const float*)d_in[6];
    const float* W2       = (const float*)d_in[7];
    const float* b2       = (const float*)d_in[8];
    const float* W3       = (const float*)d_in[9];
    // d_in[10] = b3: constant shift of scores -> softmax-invariant, unused.
    float* out = (float*)d_out;

    cudaFuncSetAttribute(lstm_kernel, cudaFuncAttributeMaxDynamicSharedMemorySize, LSTM_SMEM);
    cudaFuncSetAttribute(attn_kernel, cudaFuncAttributeMaxDynamicSharedMemorySize, ATTN_SMEM);

    xz_kernel<<<128, 512>>>(inputs, Wk, bias);
    keys_kernel<<<256, 128>>>(attended, W1, b1);
    lstm_kernel<<<8, 512, LSTM_SMEM>>>(Wr, out);
    attn_kernel<<<dim3(16, 8), 256, ATTN_SMEM>>>(attended, W2, b2, W3, out);
}